// round 1
// baseline (speedup 1.0000x reference)
#include <cuda_runtime.h>

#define N_NODES 50000
#define N_EDGES 1600000
#define IN_DIM 128
#define OUT_DIM 32
#define HEADS 4
#define HD 128           // HEADS * OUT_DIM
#define EDGE_DIM 16

#define SCAN_CHUNK 512
#define SCAN_NB 98       // ceil(50000/512)

// ---------------- device scratch (static: no allocation allowed) ----------------
__device__ float g_h[N_NODES * HD];           // 25.6 MB  h = x @ W^T
__device__ float g_WT[IN_DIM * HD];           // 64 KB    W transposed [k][j]
__device__ float g_asrc[N_NODES * HEADS];
__device__ float g_adst[N_NODES * HEADS];
__device__ int   g_cnt[N_NODES];
__device__ int   g_off[N_NODES + 1];
__device__ int   g_cur[N_NODES];
__device__ int   g_blocksum[SCAN_NB];
__device__ int   g_csr_src[N_EDGES];          // 6.4 MB
__device__ float g_csr_logit[N_EDGES * HEADS];// 25.6 MB

// ---------------- small utility kernels ----------------
__global__ void k_zero() {
    int i = blockIdx.x * blockDim.x + threadIdx.x;
    if (i < N_NODES) g_cnt[i] = 0;
}

// W [j][k] row-major -> WT [k][j]
__global__ void k_transW(const float* __restrict__ W) {
    int j = blockIdx.x;
    int k = threadIdx.x;
    g_WT[k * HD + j] = W[j * IN_DIM + k];
}

// ---------------- GEMM: h[n][j] = sum_k x[n][k] * W[j][k] ----------------
// tile: 64 nodes x 128 cols, 256 threads, each thread 4 nodes x 8 cols
__global__ __launch_bounds__(256) void k_gemm(const float* __restrict__ x) {
    __shared__ float ws[32][136];   // W chunk [kk][j], padded (544B rows, 16B aligned)
    __shared__ float xs[64][33];    // x chunk [n][kk], padded

    int tid = threadIdx.x;
    int tx = tid & 15;      // col group: cols tx*8 .. tx*8+7
    int ty = tid >> 4;      // node group: nodes ty*4 .. ty*4+3
    int n0 = blockIdx.x * 64;

    float acc[4][8];
#pragma unroll
    for (int i = 0; i < 4; i++)
#pragma unroll
        for (int j = 0; j < 8; j++) acc[i][j] = 0.f;

    for (int kc = 0; kc < IN_DIM; kc += 32) {
        __syncthreads();
        // load W chunk: rows kc..kc+31 of WT, coalesced, conflict-free store
        for (int i = tid; i < 32 * HD; i += 256) {
            int kk = i >> 7, j = i & 127;
            ws[kk][j] = g_WT[(kc + kk) * HD + j];
        }
        // load x chunk: 64 nodes x 32 k
        for (int i = tid; i < 64 * 32; i += 256) {
            int nn = i >> 5, kk = i & 31;
            int gn = n0 + nn;
            xs[nn][kk] = (gn < N_NODES) ? x[gn * IN_DIM + kc + kk] : 0.f;
        }
        __syncthreads();

#pragma unroll 8
        for (int kk = 0; kk < 32; kk++) {
            float4 w0 = *(const float4*)&ws[kk][tx * 8];
            float4 w1 = *(const float4*)&ws[kk][tx * 8 + 4];
            float wv[8] = {w0.x, w0.y, w0.z, w0.w, w1.x, w1.y, w1.z, w1.w};
#pragma unroll
            for (int i = 0; i < 4; i++) {
                float xv = xs[ty * 4 + i][kk];
#pragma unroll
                for (int j = 0; j < 8; j++)
                    acc[i][j] = fmaf(xv, wv[j], acc[i][j]);
            }
        }
    }

#pragma unroll
    for (int i = 0; i < 4; i++) {
        int gn = n0 + ty * 4 + i;
        if (gn < N_NODES) {
            float4 o0 = {acc[i][0], acc[i][1], acc[i][2], acc[i][3]};
            float4 o1 = {acc[i][4], acc[i][5], acc[i][6], acc[i][7]};
            *(float4*)&g_h[gn * HD + tx * 8]     = o0;
            *(float4*)&g_h[gn * HD + tx * 8 + 4] = o1;
        }
    }
}

// ---------------- per-node attention terms a_src / a_dst ----------------
__global__ void k_anode(const float* __restrict__ att_src,
                        const float* __restrict__ att_dst) {
    int idx = blockIdx.x * blockDim.x + threadIdx.x;
    if (idx >= N_NODES * HEADS) return;
    int n = idx >> 2, hh = idx & 3;
    const float4* hp = (const float4*)&g_h[n * HD + hh * OUT_DIM];
    const float4* ap = (const float4*)&att_src[hh * OUT_DIM];
    const float4* bp = (const float4*)&att_dst[hh * OUT_DIM];
    float s = 0.f, d = 0.f;
#pragma unroll
    for (int q = 0; q < 8; q++) {
        float4 hv = hp[q];
        float4 av = __ldg(&ap[q]);
        float4 bv = __ldg(&bp[q]);
        s = fmaf(hv.x, av.x, fmaf(hv.y, av.y, fmaf(hv.z, av.z, fmaf(hv.w, av.w, s))));
        d = fmaf(hv.x, bv.x, fmaf(hv.y, bv.y, fmaf(hv.z, bv.z, fmaf(hv.w, bv.w, d))));
    }
    g_asrc[idx] = s;
    g_adst[idx] = d;
}

// ---------------- histogram of dst ----------------
__global__ void k_hist(const int* __restrict__ ei) {
    int e = blockIdx.x * blockDim.x + threadIdx.x;
    if (e < N_EDGES) atomicAdd(&g_cnt[ei[N_EDGES + e]], 1);
}

// ---------------- 3-phase exclusive scan of counts ----------------
__global__ void k_scan1() {
    __shared__ int sh[256];
    int b = blockIdx.x, t = threadIdx.x;
    int base = b * SCAN_CHUNK;
    int i0 = base + 2 * t, i1 = i0 + 1;
    int s = 0;
    if (i0 < N_NODES) s += g_cnt[i0];
    if (i1 < N_NODES) s += g_cnt[i1];
    sh[t] = s;
    __syncthreads();
    for (int off = 128; off > 0; off >>= 1) {
        if (t < off) sh[t] += sh[t + off];
        __syncthreads();
    }
    if (t == 0) g_blocksum[b] = sh[0];
}

__global__ void k_scan2() {
    int run = 0;
    for (int b = 0; b < SCAN_NB; b++) {
        int v = g_blocksum[b];
        g_blocksum[b] = run;
        run += v;
    }
}

__global__ void k_scan3() {
    __shared__ int sh[256];
    int b = blockIdx.x, t = threadIdx.x;
    int base = b * SCAN_CHUNK;
    int i0 = base + 2 * t, i1 = i0 + 1;
    int c0 = (i0 < N_NODES) ? g_cnt[i0] : 0;
    int c1 = (i1 < N_NODES) ? g_cnt[i1] : 0;
    int mys = c0 + c1;
    sh[t] = mys;
    __syncthreads();
    for (int off = 1; off < 256; off <<= 1) {
        int v = (t >= off) ? sh[t - off] : 0;
        __syncthreads();
        sh[t] += v;
        __syncthreads();
    }
    int excl = sh[t] - mys + g_blocksum[b];
    if (i0 < N_NODES) { g_off[i0] = excl;      g_cur[i0] = excl; }
    if (i1 < N_NODES) { g_off[i1] = excl + c0; g_cur[i1] = excl + c0; }
    if (b == 0 && t == 0) g_off[N_NODES] = N_EDGES;
}

// ---------------- edge pass: logits + CSR scatter ----------------
__global__ __launch_bounds__(256) void k_edge(const int* __restrict__ ei,
                                              const float* __restrict__ ea,
                                              const float* __restrict__ Wedge) {
    __shared__ float we[HEADS * EDGE_DIM];
    if (threadIdx.x < HEADS * EDGE_DIM) we[threadIdx.x] = Wedge[threadIdx.x];
    __syncthreads();

    int e = blockIdx.x * blockDim.x + threadIdx.x;
    if (e >= N_EDGES) return;

    int src = ei[e];
    int dst = ei[N_EDGES + e];

    const float4* ep = (const float4*)&ea[e * EDGE_DIM];
    float4 e0 = ep[0], e1 = ep[1], e2 = ep[2], e3 = ep[3];
    float ev[16] = {e0.x, e0.y, e0.z, e0.w, e1.x, e1.y, e1.z, e1.w,
                    e2.x, e2.y, e2.z, e2.w, e3.x, e3.y, e3.z, e3.w};

    float lg[4];
#pragma unroll
    for (int h = 0; h < 4; h++) {
        float s = 0.f;
#pragma unroll
        for (int k = 0; k < 16; k++) s = fmaf(ev[k], we[h * 16 + k], s);
        lg[h] = s;
    }

    float4 a4 = *(const float4*)&g_asrc[src * 4];
    float4 b4 = *(const float4*)&g_adst[dst * 4];
    lg[0] += a4.x + b4.x;
    lg[1] += a4.y + b4.y;
    lg[2] += a4.z + b4.z;
    lg[3] += a4.w + b4.w;
#pragma unroll
    for (int h = 0; h < 4; h++)
        lg[h] = (lg[h] > 0.f) ? lg[h] : 0.2f * lg[h];

    int pos = atomicAdd(&g_cur[dst], 1);
    g_csr_src[pos] = src;
    float4 l4 = {lg[0], lg[1], lg[2], lg[3]};
    *(float4*)&g_csr_logit[pos * 4] = l4;
}

// ---------------- aggregation: warp per node, no atomics ----------------
__global__ __launch_bounds__(256) void k_agg(const float* __restrict__ bias,
                                             float* __restrict__ out) {
    __shared__ float s_alpha[8][32][4];
    __shared__ int   s_src[8][32];

    int warp = threadIdx.x >> 5;
    int lane = threadIdx.x & 31;
    int n = blockIdx.x * 8 + warp;
    if (n >= N_NODES) return;

    int beg = g_off[n];
    int end = g_off[n + 1];
    int myh = lane >> 3;

    // pass 1: denom per head (no max-subtraction needed: logits are O(1))
    float d0 = 0.f, d1 = 0.f, d2 = 0.f, d3 = 0.f;
    for (int i = beg + lane; i < end; i += 32) {
        float4 l4 = *(const float4*)&g_csr_logit[i * 4];
        d0 += __expf(l4.x);
        d1 += __expf(l4.y);
        d2 += __expf(l4.z);
        d3 += __expf(l4.w);
    }
#pragma unroll
    for (int off = 16; off > 0; off >>= 1) {
        d0 += __shfl_xor_sync(0xffffffffu, d0, off);
        d1 += __shfl_xor_sync(0xffffffffu, d1, off);
        d2 += __shfl_xor_sync(0xffffffffu, d2, off);
        d3 += __shfl_xor_sync(0xffffffffu, d3, off);
    }
    float i0 = 1.f / (d0 + 1e-16f);
    float i1 = 1.f / (d1 + 1e-16f);
    float i2 = 1.f / (d2 + 1e-16f);
    float i3 = 1.f / (d3 + 1e-16f);

    // pass 2: alpha-weighted gather of h[src]
    float4 acc = {0.f, 0.f, 0.f, 0.f};
    for (int c = beg; c < end; c += 32) {
        int i = c + lane;
        int nb = min(32, end - c);
        if (lane < nb) {
            float4 l4 = *(const float4*)&g_csr_logit[i * 4];
            s_src[warp][lane] = g_csr_src[i];
            s_alpha[warp][lane][0] = __expf(l4.x) * i0;
            s_alpha[warp][lane][1] = __expf(l4.y) * i1;
            s_alpha[warp][lane][2] = __expf(l4.z) * i2;
            s_alpha[warp][lane][3] = __expf(l4.w) * i3;
        }
        __syncwarp();
        for (int j = 0; j < nb; j++) {
            int sj = s_src[warp][j];
            float a = s_alpha[warp][j][myh];
            float4 hv = *(const float4*)&g_h[sj * HD + lane * 4];
            acc.x = fmaf(a, hv.x, acc.x);
            acc.y = fmaf(a, hv.y, acc.y);
            acc.z = fmaf(a, hv.z, acc.z);
            acc.w = fmaf(a, hv.w, acc.w);
        }
        __syncwarp();
    }

    // reduce over heads (lanes l, l^8, l^16, l^24 hold heads 0..3, same dims)
    acc.x += __shfl_xor_sync(0xffffffffu, acc.x, 8);
    acc.y += __shfl_xor_sync(0xffffffffu, acc.y, 8);
    acc.z += __shfl_xor_sync(0xffffffffu, acc.z, 8);
    acc.w += __shfl_xor_sync(0xffffffffu, acc.w, 8);
    acc.x += __shfl_xor_sync(0xffffffffu, acc.x, 16);
    acc.y += __shfl_xor_sync(0xffffffffu, acc.y, 16);
    acc.z += __shfl_xor_sync(0xffffffffu, acc.z, 16);
    acc.w += __shfl_xor_sync(0xffffffffu, acc.w, 16);

    if (lane < 8) {
        float4 b4 = *(const float4*)&bias[lane * 4];
        float4 o;
        o.x = acc.x * 0.25f + b4.x;
        o.y = acc.y * 0.25f + b4.y;
        o.z = acc.z * 0.25f + b4.z;
        o.w = acc.w * 0.25f + b4.w;
        *(float4*)&out[n * OUT_DIM + lane * 4] = o;
    }
}

// ---------------- launch ----------------
extern "C" void kernel_launch(void* const* d_in, const int* in_sizes, int n_in,
                              void* d_out, int out_size) {
    const float* x    = (const float*)d_in[0];
    const int*   ei   = (const int*)  d_in[1];
    const float* ea   = (const float*)d_in[2];
    const float* Wl   = (const float*)d_in[3];
    const float* as   = (const float*)d_in[4];
    const float* ad   = (const float*)d_in[5];
    const float* bias = (const float*)d_in[6];
    const float* We   = (const float*)d_in[7];
    float* out = (float*)d_out;

    k_zero  <<<(N_NODES + 255) / 256, 256>>>();
    k_transW<<<IN_DIM, HD>>>(Wl);
    k_gemm  <<<(N_NODES + 63) / 64, 256>>>(x);
    k_anode <<<(N_NODES * HEADS + 255) / 256, 256>>>(as, ad);
    k_hist  <<<(N_EDGES + 511) / 512, 512>>>(ei);
    k_scan1 <<<SCAN_NB, 256>>>();
    k_scan2 <<<1, 1>>>();
    k_scan3 <<<SCAN_NB, 256>>>();
    k_edge  <<<(N_EDGES + 255) / 256, 256>>>(ei, ea, We);
    k_agg   <<<(N_NODES + 7) / 8, 256>>>(bias, out);
}

// round 2
// speedup vs baseline: 1.0656x; 1.0656x over previous
#include <cuda_runtime.h>
#include <cuda_fp16.h>

#define N_NODES 50000
#define N_EDGES 1600000
#define IN_DIM 128
#define OUT_DIM 32
#define HEADS 4
#define HD 128           // HEADS * OUT_DIM
#define EDGE_DIM 16

#define SCAN_CHUNK 512
#define SCAN_NB 98       // ceil(50000/512)

// ---------------- device scratch (static: no allocation allowed) ----------------
__device__ __half g_hh[N_NODES * HD];         // 12.8 MB  h = x @ W^T (fp16)
__device__ float g_WT[IN_DIM * HD];           // 64 KB    W transposed [k][j]
__device__ float g_asrc[N_NODES * HEADS];
__device__ float g_adst[N_NODES * HEADS];
__device__ int   g_cnt[N_NODES];
__device__ int   g_off[N_NODES + 1];
__device__ int   g_cur[N_NODES];
__device__ int   g_blocksum[SCAN_NB];
__device__ int   g_csr_src[N_EDGES];          // 6.4 MB
__device__ float g_csr_logit[N_EDGES * HEADS];// 25.6 MB

// ---------------- small utility kernels ----------------
__global__ void k_zero() {
    int i = blockIdx.x * blockDim.x + threadIdx.x;
    if (i < N_NODES) g_cnt[i] = 0;
}

// W [j][k] row-major -> WT [k][j]
__global__ void k_transW(const float* __restrict__ W) {
    int j = blockIdx.x;
    int k = threadIdx.x;
    g_WT[k * HD + j] = W[j * IN_DIM + k];
}

// ---------------- GEMM: h[n][j] = sum_k x[n][k]*W[j][k]; fused a_src/a_dst ----------------
// tile: 64 nodes x 128 cols, 256 threads, each thread 4 nodes x 8 cols.
// Cols tx*8..tx*8+7 lie inside head (tx>>2); lanes {4h..4h+3} (same ty) shuffle-reduce
// the per-head attention dot products, then write g_hh in fp16.
__global__ __launch_bounds__(256) void k_gemm(const float* __restrict__ x,
                                              const float* __restrict__ att_src,
                                              const float* __restrict__ att_dst) {
    __shared__ float ws[32][136];   // W chunk [kk][j], padded
    __shared__ float xs[64][33];    // x chunk [n][kk], padded

    int tid = threadIdx.x;
    int tx = tid & 15;      // col group: cols tx*8 .. tx*8+7
    int ty = tid >> 4;      // node group: nodes ty*4 .. ty*4+3
    int n0 = blockIdx.x * 64;

    // attention vectors for this thread's 8 columns (flat layout = att[tx*8+j])
    float avs[8], avd[8];
    {
        float4 s0 = __ldg((const float4*)&att_src[tx * 8]);
        float4 s1 = __ldg((const float4*)&att_src[tx * 8 + 4]);
        float4 d0 = __ldg((const float4*)&att_dst[tx * 8]);
        float4 d1 = __ldg((const float4*)&att_dst[tx * 8 + 4]);
        avs[0]=s0.x; avs[1]=s0.y; avs[2]=s0.z; avs[3]=s0.w;
        avs[4]=s1.x; avs[5]=s1.y; avs[6]=s1.z; avs[7]=s1.w;
        avd[0]=d0.x; avd[1]=d0.y; avd[2]=d0.z; avd[3]=d0.w;
        avd[4]=d1.x; avd[5]=d1.y; avd[6]=d1.z; avd[7]=d1.w;
    }

    float acc[4][8];
#pragma unroll
    for (int i = 0; i < 4; i++)
#pragma unroll
        for (int j = 0; j < 8; j++) acc[i][j] = 0.f;

    for (int kc = 0; kc < IN_DIM; kc += 32) {
        __syncthreads();
        for (int i = tid; i < 32 * HD; i += 256) {
            int kk = i >> 7, j = i & 127;
            ws[kk][j] = g_WT[(kc + kk) * HD + j];
        }
        for (int i = tid; i < 64 * 32; i += 256) {
            int nn = i >> 5, kk = i & 31;
            int gn = n0 + nn;
            xs[nn][kk] = (gn < N_NODES) ? x[gn * IN_DIM + kc + kk] : 0.f;
        }
        __syncthreads();

#pragma unroll 8
        for (int kk = 0; kk < 32; kk++) {
            float4 w0 = *(const float4*)&ws[kk][tx * 8];
            float4 w1 = *(const float4*)&ws[kk][tx * 8 + 4];
            float wv[8] = {w0.x, w0.y, w0.z, w0.w, w1.x, w1.y, w1.z, w1.w};
#pragma unroll
            for (int i = 0; i < 4; i++) {
                float xv = xs[ty * 4 + i][kk];
#pragma unroll
                for (int j = 0; j < 8; j++)
                    acc[i][j] = fmaf(xv, wv[j], acc[i][j]);
            }
        }
    }

    // ---- fused per-node attention terms ----
    float ps[4], pd[4];
#pragma unroll
    for (int i = 0; i < 4; i++) {
        float s = 0.f, d = 0.f;
#pragma unroll
        for (int j = 0; j < 8; j++) {
            s = fmaf(acc[i][j], avs[j], s);
            d = fmaf(acc[i][j], avd[j], d);
        }
        ps[i] = s; pd[i] = d;
    }
#pragma unroll
    for (int off = 1; off < 4; off <<= 1) {
#pragma unroll
        for (int i = 0; i < 4; i++) {
            ps[i] += __shfl_xor_sync(0xffffffffu, ps[i], off);
            pd[i] += __shfl_xor_sync(0xffffffffu, pd[i], off);
        }
    }
    int head = tx >> 2;
    bool wr_att = ((tx & 3) == 0);

#pragma unroll
    for (int i = 0; i < 4; i++) {
        int gn = n0 + ty * 4 + i;
        if (gn < N_NODES) {
            __half2 h0 = __floats2half2_rn(acc[i][0], acc[i][1]);
            __half2 h1 = __floats2half2_rn(acc[i][2], acc[i][3]);
            __half2 h2 = __floats2half2_rn(acc[i][4], acc[i][5]);
            __half2 h3 = __floats2half2_rn(acc[i][6], acc[i][7]);
            uint4 v;
            v.x = *(const unsigned*)&h0;
            v.y = *(const unsigned*)&h1;
            v.z = *(const unsigned*)&h2;
            v.w = *(const unsigned*)&h3;
            *(uint4*)&g_hh[gn * HD + tx * 8] = v;
            if (wr_att) {
                g_asrc[gn * HEADS + head] = ps[i];
                g_adst[gn * HEADS + head] = pd[i];
            }
        }
    }
}

// ---------------- histogram of dst ----------------
__global__ void k_hist(const int* __restrict__ ei) {
    int e = blockIdx.x * blockDim.x + threadIdx.x;
    if (e < N_EDGES) atomicAdd(&g_cnt[ei[N_EDGES + e]], 1);
}

// ---------------- 3-phase exclusive scan of counts ----------------
__global__ void k_scan1() {
    __shared__ int sh[256];
    int b = blockIdx.x, t = threadIdx.x;
    int base = b * SCAN_CHUNK;
    int i0 = base + 2 * t, i1 = i0 + 1;
    int s = 0;
    if (i0 < N_NODES) s += g_cnt[i0];
    if (i1 < N_NODES) s += g_cnt[i1];
    sh[t] = s;
    __syncthreads();
    for (int off = 128; off > 0; off >>= 1) {
        if (t < off) sh[t] += sh[t + off];
        __syncthreads();
    }
    if (t == 0) g_blocksum[b] = sh[0];
}

__global__ void k_scan2() {
    int run = 0;
    for (int b = 0; b < SCAN_NB; b++) {
        int v = g_blocksum[b];
        g_blocksum[b] = run;
        run += v;
    }
}

__global__ void k_scan3() {
    __shared__ int sh[256];
    int b = blockIdx.x, t = threadIdx.x;
    int base = b * SCAN_CHUNK;
    int i0 = base + 2 * t, i1 = i0 + 1;
    int c0 = (i0 < N_NODES) ? g_cnt[i0] : 0;
    int c1 = (i1 < N_NODES) ? g_cnt[i1] : 0;
    int mys = c0 + c1;
    sh[t] = mys;
    __syncthreads();
    for (int off = 1; off < 256; off <<= 1) {
        int v = (t >= off) ? sh[t - off] : 0;
        __syncthreads();
        sh[t] += v;
        __syncthreads();
    }
    int excl = sh[t] - mys + g_blocksum[b];
    if (i0 < N_NODES) { g_off[i0] = excl;      g_cur[i0] = excl; }
    if (i1 < N_NODES) { g_off[i1] = excl + c0; g_cur[i1] = excl + c0; }
    if (b == 0 && t == 0) g_off[N_NODES] = N_EDGES;
}

// ---------------- edge pass: logits + CSR scatter ----------------
__global__ __launch_bounds__(256) void k_edge(const int* __restrict__ ei,
                                              const float* __restrict__ ea,
                                              const float* __restrict__ Wedge) {
    __shared__ float we[HEADS * EDGE_DIM];
    if (threadIdx.x < HEADS * EDGE_DIM) we[threadIdx.x] = Wedge[threadIdx.x];
    __syncthreads();

    int e = blockIdx.x * blockDim.x + threadIdx.x;
    if (e >= N_EDGES) return;

    int src = ei[e];
    int dst = ei[N_EDGES + e];

    const float4* ep = (const float4*)&ea[e * EDGE_DIM];
    float4 e0 = ep[0], e1 = ep[1], e2 = ep[2], e3 = ep[3];
    float ev[16] = {e0.x, e0.y, e0.z, e0.w, e1.x, e1.y, e1.z, e1.w,
                    e2.x, e2.y, e2.z, e2.w, e3.x, e3.y, e3.z, e3.w};

    float lg[4];
#pragma unroll
    for (int h = 0; h < 4; h++) {
        float s = 0.f;
#pragma unroll
        for (int k = 0; k < 16; k++) s = fmaf(ev[k], we[h * 16 + k], s);
        lg[h] = s;
    }

    float4 a4 = *(const float4*)&g_asrc[src * 4];
    float4 b4 = *(const float4*)&g_adst[dst * 4];
    lg[0] += a4.x + b4.x;
    lg[1] += a4.y + b4.y;
    lg[2] += a4.z + b4.z;
    lg[3] += a4.w + b4.w;
#pragma unroll
    for (int h = 0; h < 4; h++)
        lg[h] = (lg[h] > 0.f) ? lg[h] : 0.2f * lg[h];

    int pos = atomicAdd(&g_cur[dst], 1);
    g_csr_src[pos] = src;
    float4 l4 = {lg[0], lg[1], lg[2], lg[3]};
    *(float4*)&g_csr_logit[pos * 4] = l4;
}

// ---------------- aggregation: warp per node, fp16 h gather, no atomics ----------------
__global__ __launch_bounds__(256) void k_agg(const float* __restrict__ bias,
                                             float* __restrict__ out) {
    __shared__ float s_alpha[8][32][4];
    __shared__ int   s_src[8][32];

    int warp = threadIdx.x >> 5;
    int lane = threadIdx.x & 31;
    int n = blockIdx.x * 8 + warp;
    if (n >= N_NODES) return;

    int beg = g_off[n];
    int end = g_off[n + 1];
    int myh = lane >> 3;

    // pass 1: denom per head (logits O(1), exp never overflows; max-shift unneeded)
    float d0 = 0.f, d1 = 0.f, d2 = 0.f, d3 = 0.f;
    for (int i = beg + lane; i < end; i += 32) {
        float4 l4 = *(const float4*)&g_csr_logit[i * 4];
        d0 += __expf(l4.x);
        d1 += __expf(l4.y);
        d2 += __expf(l4.z);
        d3 += __expf(l4.w);
    }
#pragma unroll
    for (int off = 16; off > 0; off >>= 1) {
        d0 += __shfl_xor_sync(0xffffffffu, d0, off);
        d1 += __shfl_xor_sync(0xffffffffu, d1, off);
        d2 += __shfl_xor_sync(0xffffffffu, d2, off);
        d3 += __shfl_xor_sync(0xffffffffu, d3, off);
    }
    float i0 = 1.f / (d0 + 1e-16f);
    float i1 = 1.f / (d1 + 1e-16f);
    float i2 = 1.f / (d2 + 1e-16f);
    float i3 = 1.f / (d3 + 1e-16f);

    // pass 2: alpha-weighted gather of h[src] (fp16 rows, 256B each)
    float4 acc = {0.f, 0.f, 0.f, 0.f};
    for (int c = beg; c < end; c += 32) {
        int i = c + lane;
        int nb = min(32, end - c);
        if (lane < nb) {
            float4 l4 = *(const float4*)&g_csr_logit[i * 4];
            s_src[warp][lane] = g_csr_src[i];
            s_alpha[warp][lane][0] = __expf(l4.x) * i0;
            s_alpha[warp][lane][1] = __expf(l4.y) * i1;
            s_alpha[warp][lane][2] = __expf(l4.z) * i2;
            s_alpha[warp][lane][3] = __expf(l4.w) * i3;
        }
        __syncwarp();
        for (int j = 0; j < nb; j++) {
            int sj = s_src[warp][j];
            float a = s_alpha[warp][j][myh];
            uint2 raw = *(const uint2*)&g_hh[sj * HD + lane * 4];
            __half2 p01 = *(const __half2*)&raw.x;
            __half2 p23 = *(const __half2*)&raw.y;
            float2 f01 = __half22float2(p01);
            float2 f23 = __half22float2(p23);
            acc.x = fmaf(a, f01.x, acc.x);
            acc.y = fmaf(a, f01.y, acc.y);
            acc.z = fmaf(a, f23.x, acc.z);
            acc.w = fmaf(a, f23.y, acc.w);
        }
        __syncwarp();
    }

    // reduce over heads (lanes l, l^8, l^16, l^24 hold heads 0..3, same dims)
    acc.x += __shfl_xor_sync(0xffffffffu, acc.x, 8);
    acc.y += __shfl_xor_sync(0xffffffffu, acc.y, 8);
    acc.z += __shfl_xor_sync(0xffffffffu, acc.z, 8);
    acc.w += __shfl_xor_sync(0xffffffffu, acc.w, 8);
    acc.x += __shfl_xor_sync(0xffffffffu, acc.x, 16);
    acc.y += __shfl_xor_sync(0xffffffffu, acc.y, 16);
    acc.z += __shfl_xor_sync(0xffffffffu, acc.z, 16);
    acc.w += __shfl_xor_sync(0xffffffffu, acc.w, 16);

    if (lane < 8) {
        float4 b4 = *(const float4*)&bias[lane * 4];
        float4 o;
        o.x = acc.x * 0.25f + b4.x;
        o.y = acc.y * 0.25f + b4.y;
        o.z = acc.z * 0.25f + b4.z;
        o.w = acc.w * 0.25f + b4.w;
        *(float4*)&out[n * OUT_DIM + lane * 4] = o;
    }
}

// ---------------- launch ----------------
extern "C" void kernel_launch(void* const* d_in, const int* in_sizes, int n_in,
                              void* d_out, int out_size) {
    const float* x    = (const float*)d_in[0];
    const int*   ei   = (const int*)  d_in[1];
    const float* ea   = (const float*)d_in[2];
    const float* Wl   = (const float*)d_in[3];
    const float* as   = (const float*)d_in[4];
    const float* ad   = (const float*)d_in[5];
    const float* bias = (const float*)d_in[6];
    const float* We   = (const float*)d_in[7];
    float* out = (float*)d_out;

    k_zero  <<<(N_NODES + 255) / 256, 256>>>();
    k_transW<<<IN_DIM, HD>>>(Wl);
    k_gemm  <<<(N_NODES + 63) / 64, 256>>>(x, as, ad);
    k_hist  <<<(N_EDGES + 511) / 512, 512>>>(ei);
    k_scan1 <<<SCAN_NB, 256>>>();
    k_scan2 <<<1, 1>>>();
    k_scan3 <<<SCAN_NB, 256>>>();
    k_edge  <<<(N_EDGES + 255) / 256, 256>>>(ei, ea, We);
    k_agg   <<<(N_NODES + 7) / 8, 256>>>(bias, out);
}

// round 4
// speedup vs baseline: 1.0843x; 1.0175x over previous
#include <cuda_runtime.h>
#include <cuda_fp16.h>

#define N_NODES 50000
#define N_EDGES 1600000
#define IN_DIM 128
#define OUT_DIM 32
#define HEADS 4
#define HD 128           // HEADS * OUT_DIM
#define EDGE_DIM 16

#define SCAN_CHUNK 512
#define SCAN_NB 98       // ceil(50000/512)

// ---------------- device scratch (static: no allocation allowed) ----------------
__device__ __half g_hh[N_NODES * HD];         // 12.8 MB  h (fp16)
__device__ float g_WT[IN_DIM * HD];           // 64 KB
__device__ float g_asrc[N_NODES * HEADS];
__device__ float g_adst[N_NODES * HEADS];
__device__ int   g_cnt[N_NODES];
__device__ int   g_off[N_NODES + 1];
__device__ int   g_rank[N_EDGES];             // 6.4 MB rank of edge within its dst segment
__device__ int   g_blocksum[SCAN_NB];
__device__ int   g_csr_src[N_EDGES];          // 6.4 MB
__device__ uint2 g_csr_exp[N_EDGES];          // 12.8 MB: 4 x fp16 exp(logit) per edge

// ---------------- small utility kernels ----------------
__global__ void k_zero() {
    int i = blockIdx.x * blockDim.x + threadIdx.x;
    if (i < N_NODES) g_cnt[i] = 0;
}

__global__ void k_transW(const float* __restrict__ W) {
    int j = blockIdx.x;
    int k = threadIdx.x;
    g_WT[k * HD + j] = W[j * IN_DIM + k];
}

// ---------------- GEMM: 128-node x 128-col tile, 256 thr, 8x8 per thread ----------------
__global__ __launch_bounds__(256) void k_gemm(const float* __restrict__ x,
                                              const float* __restrict__ att_src,
                                              const float* __restrict__ att_dst) {
    __shared__ float ws[32][136];   // W chunk [kk][j], padded
    __shared__ float xs[128][33];   // x chunk [n][kk], padded

    int tid = threadIdx.x;
    int tx = tid & 15;      // cols tx*8 .. tx*8+7
    int ty = tid >> 4;      // nodes ty*8 .. ty*8+7
    int n0 = blockIdx.x * 128;

    float avs[8], avd[8];
    {
        float4 s0 = __ldg((const float4*)&att_src[tx * 8]);
        float4 s1 = __ldg((const float4*)&att_src[tx * 8 + 4]);
        float4 d0 = __ldg((const float4*)&att_dst[tx * 8]);
        float4 d1 = __ldg((const float4*)&att_dst[tx * 8 + 4]);
        avs[0]=s0.x; avs[1]=s0.y; avs[2]=s0.z; avs[3]=s0.w;
        avs[4]=s1.x; avs[5]=s1.y; avs[6]=s1.z; avs[7]=s1.w;
        avd[0]=d0.x; avd[1]=d0.y; avd[2]=d0.z; avd[3]=d0.w;
        avd[4]=d1.x; avd[5]=d1.y; avd[6]=d1.z; avd[7]=d1.w;
    }

    float acc[8][8];
#pragma unroll
    for (int i = 0; i < 8; i++)
#pragma unroll
        for (int j = 0; j < 8; j++) acc[i][j] = 0.f;

    for (int kc = 0; kc < IN_DIM; kc += 32) {
        __syncthreads();
        for (int i = tid; i < 32 * HD; i += 256) {
            int kk = i >> 7, j = i & 127;
            ws[kk][j] = g_WT[(kc + kk) * HD + j];
        }
        for (int i = tid; i < 128 * 32; i += 256) {
            int nn = i >> 5, kk = i & 31;
            int gn = n0 + nn;
            xs[nn][kk] = (gn < N_NODES) ? x[gn * IN_DIM + kc + kk] : 0.f;
        }
        __syncthreads();

#pragma unroll 4
        for (int kk = 0; kk < 32; kk++) {
            float4 w0 = *(const float4*)&ws[kk][tx * 8];
            float4 w1 = *(const float4*)&ws[kk][tx * 8 + 4];
            float wv[8] = {w0.x, w0.y, w0.z, w0.w, w1.x, w1.y, w1.z, w1.w};
            float xv[8];
#pragma unroll
            for (int i = 0; i < 8; i++) xv[i] = xs[ty * 8 + i][kk];
#pragma unroll
            for (int i = 0; i < 8; i++)
#pragma unroll
                for (int j = 0; j < 8; j++)
                    acc[i][j] = fmaf(xv[i], wv[j], acc[i][j]);
        }
    }

    // fused attention terms: shuffle-reduce over the 4 lanes covering one head
    float ps[8], pd[8];
#pragma unroll
    for (int i = 0; i < 8; i++) {
        float s = 0.f, d = 0.f;
#pragma unroll
        for (int j = 0; j < 8; j++) {
            s = fmaf(acc[i][j], avs[j], s);
            d = fmaf(acc[i][j], avd[j], d);
        }
        ps[i] = s; pd[i] = d;
    }
#pragma unroll
    for (int off = 1; off < 4; off <<= 1) {
#pragma unroll
        for (int i = 0; i < 8; i++) {
            ps[i] += __shfl_xor_sync(0xffffffffu, ps[i], off);
            pd[i] += __shfl_xor_sync(0xffffffffu, pd[i], off);
        }
    }
    int head = tx >> 2;
    bool wr_att = ((tx & 3) == 0);

#pragma unroll
    for (int i = 0; i < 8; i++) {
        int gn = n0 + ty * 8 + i;
        if (gn < N_NODES) {
            __half2 h0 = __floats2half2_rn(acc[i][0], acc[i][1]);
            __half2 h1 = __floats2half2_rn(acc[i][2], acc[i][3]);
            __half2 h2 = __floats2half2_rn(acc[i][4], acc[i][5]);
            __half2 h3 = __floats2half2_rn(acc[i][6], acc[i][7]);
            uint4 v;
            v.x = *(const unsigned*)&h0;
            v.y = *(const unsigned*)&h1;
            v.z = *(const unsigned*)&h2;
            v.w = *(const unsigned*)&h3;
            *(uint4*)&g_hh[gn * HD + tx * 8] = v;
            if (wr_att) {
                g_asrc[gn * HEADS + head] = ps[i];
                g_adst[gn * HEADS + head] = pd[i];
            }
        }
    }
}

// ---------------- histogram of dst + rank assignment ----------------
__global__ void k_hist(const int* __restrict__ ei) {
    int e = blockIdx.x * blockDim.x + threadIdx.x;
    if (e < N_EDGES) {
        int d = ei[N_EDGES + e];
        g_rank[e] = atomicAdd(&g_cnt[d], 1);
    }
}

// ---------------- 3-phase exclusive scan of counts ----------------
__global__ void k_scan1() {
    __shared__ int sh[256];
    int b = blockIdx.x, t = threadIdx.x;
    int base = b * SCAN_CHUNK;
    int i0 = base + 2 * t, i1 = i0 + 1;
    int s = 0;
    if (i0 < N_NODES) s += g_cnt[i0];
    if (i1 < N_NODES) s += g_cnt[i1];
    sh[t] = s;
    __syncthreads();
    for (int off = 128; off > 0; off >>= 1) {
        if (t < off) sh[t] += sh[t + off];
        __syncthreads();
    }
    if (t == 0) g_blocksum[b] = sh[0];
}

__global__ void k_scan2() {
    int run = 0;
    for (int b = 0; b < SCAN_NB; b++) {
        int v = g_blocksum[b];
        g_blocksum[b] = run;
        run += v;
    }
}

__global__ void k_scan3() {
    __shared__ int sh[256];
    int b = blockIdx.x, t = threadIdx.x;
    int base = b * SCAN_CHUNK;
    int i0 = base + 2 * t, i1 = i0 + 1;
    int c0 = (i0 < N_NODES) ? g_cnt[i0] : 0;
    int c1 = (i1 < N_NODES) ? g_cnt[i1] : 0;
    int mys = c0 + c1;
    sh[t] = mys;
    __syncthreads();
    for (int off = 1; off < 256; off <<= 1) {
        int v = (t >= off) ? sh[t - off] : 0;
        __syncthreads();
        sh[t] += v;
        __syncthreads();
    }
    int excl = sh[t] - mys + g_blocksum[b];
    if (i0 < N_NODES) g_off[i0] = excl;
    if (i1 < N_NODES) g_off[i1] = excl + c0;
    if (b == 0 && t == 0) g_off[N_NODES] = N_EDGES;
}

// ---------------- edge pass: logits -> exp (fp16) + CSR scatter, no atomics ----------------
__global__ __launch_bounds__(256) void k_edge(const int* __restrict__ ei,
                                              const float* __restrict__ ea,
                                              const float* __restrict__ Wedge) {
    __shared__ float we[HEADS * EDGE_DIM];
    if (threadIdx.x < HEADS * EDGE_DIM) we[threadIdx.x] = Wedge[threadIdx.x];
    __syncthreads();

    int e = blockIdx.x * blockDim.x + threadIdx.x;
    if (e >= N_EDGES) return;

    int src = ei[e];
    int dst = ei[N_EDGES + e];

    const float4* ep = (const float4*)&ea[e * EDGE_DIM];
    float4 e0 = ep[0], e1 = ep[1], e2 = ep[2], e3 = ep[3];
    float ev[16] = {e0.x, e0.y, e0.z, e0.w, e1.x, e1.y, e1.z, e1.w,
                    e2.x, e2.y, e2.z, e2.w, e3.x, e3.y, e3.z, e3.w};

    float lg[4];
#pragma unroll
    for (int h = 0; h < 4; h++) {
        float s = 0.f;
#pragma unroll
        for (int k = 0; k < 16; k++) s = fmaf(ev[k], we[h * 16 + k], s);
        lg[h] = s;
    }

    float4 a4 = *(const float4*)&g_asrc[src * 4];
    float4 b4 = *(const float4*)&g_adst[dst * 4];
    lg[0] += a4.x + b4.x;
    lg[1] += a4.y + b4.y;
    lg[2] += a4.z + b4.z;
    lg[3] += a4.w + b4.w;
#pragma unroll
    for (int h = 0; h < 4; h++) {
        float v = (lg[h] > 0.f) ? lg[h] : 0.2f * lg[h];
        lg[h] = __expf(v);
    }

    int pos = g_off[dst] + g_rank[e];
    g_csr_src[pos] = src;
    __half2 x01 = __floats2half2_rn(lg[0], lg[1]);
    __half2 x23 = __floats2half2_rn(lg[2], lg[3]);
    uint2 pk;
    pk.x = *(const unsigned*)&x01;
    pk.y = *(const unsigned*)&x23;
    g_csr_exp[pos] = pk;
}

// ---------------- aggregation: warp per node, MLP-unrolled fp16 gather ----------------
__global__ __launch_bounds__(256) void k_agg(const float* __restrict__ bias,
                                             float* __restrict__ out) {
    __shared__ float s_alpha[8][32][4];
    __shared__ int   s_src[8][32];

    int warp = threadIdx.x >> 5;
    int lane = threadIdx.x & 31;
    int n = blockIdx.x * 8 + warp;
    if (n >= N_NODES) return;

    int beg = g_off[n];
    int end = g_off[n + 1];
    int myh = lane >> 3;

    // pass 1: denom per head (exp already computed, fp16)
    float d0 = 0.f, d1 = 0.f, d2 = 0.f, d3 = 0.f;
    for (int i = beg + lane; i < end; i += 32) {
        uint2 r = g_csr_exp[i];
        float2 f01 = __half22float2(*(const __half2*)&r.x);
        float2 f23 = __half22float2(*(const __half2*)&r.y);
        d0 += f01.x; d1 += f01.y; d2 += f23.x; d3 += f23.y;
    }
#pragma unroll
    for (int off = 16; off > 0; off >>= 1) {
        d0 += __shfl_xor_sync(0xffffffffu, d0, off);
        d1 += __shfl_xor_sync(0xffffffffu, d1, off);
        d2 += __shfl_xor_sync(0xffffffffu, d2, off);
        d3 += __shfl_xor_sync(0xffffffffu, d3, off);
    }
    float i0 = 1.f / (d0 + 1e-16f);
    float i1 = 1.f / (d1 + 1e-16f);
    float i2 = 1.f / (d2 + 1e-16f);
    float i3 = 1.f / (d3 + 1e-16f);

    // pass 2: alpha-weighted gather of h[src], 4 loads in flight
    float4 acc = {0.f, 0.f, 0.f, 0.f};
    const __half* hh = g_hh;
    for (int c = beg; c < end; c += 32) {
        int i = c + lane;
        int nb = min(32, end - c);
        if (lane < nb) {
            uint2 r = g_csr_exp[i];
            float2 f01 = __half22float2(*(const __half2*)&r.x);
            float2 f23 = __half22float2(*(const __half2*)&r.y);
            s_src[warp][lane] = g_csr_src[i];
            s_alpha[warp][lane][0] = f01.x * i0;
            s_alpha[warp][lane][1] = f01.y * i1;
            s_alpha[warp][lane][2] = f23.x * i2;
            s_alpha[warp][lane][3] = f23.y * i3;
        }
        __syncwarp();
        int j = 0;
        for (; j + 4 <= nb; j += 4) {
            int sj0 = s_src[warp][j + 0];
            int sj1 = s_src[warp][j + 1];
            int sj2 = s_src[warp][j + 2];
            int sj3 = s_src[warp][j + 3];
            uint2 r0 = *(const uint2*)&hh[sj0 * HD + lane * 4];
            uint2 r1 = *(const uint2*)&hh[sj1 * HD + lane * 4];
            uint2 r2 = *(const uint2*)&hh[sj2 * HD + lane * 4];
            uint2 r3 = *(const uint2*)&hh[sj3 * HD + lane * 4];
            float a0 = s_alpha[warp][j + 0][myh];
            float a1 = s_alpha[warp][j + 1][myh];
            float a2 = s_alpha[warp][j + 2][myh];
            float a3 = s_alpha[warp][j + 3][myh];
            float2 f;
            f = __half22float2(*(const __half2*)&r0.x); acc.x = fmaf(a0, f.x, acc.x); acc.y = fmaf(a0, f.y, acc.y);
            f = __half22float2(*(const __half2*)&r0.y); acc.z = fmaf(a0, f.x, acc.z); acc.w = fmaf(a0, f.y, acc.w);
            f = __half22float2(*(const __half2*)&r1.x); acc.x = fmaf(a1, f.x, acc.x); acc.y = fmaf(a1, f.y, acc.y);
            f = __half22float2(*(const __half2*)&r1.y); acc.z = fmaf(a1, f.x, acc.z); acc.w = fmaf(a1, f.y, acc.w);
            f = __half22float2(*(const __half2*)&r2.x); acc.x = fmaf(a2, f.x, acc.x); acc.y = fmaf(a2, f.y, acc.y);
            f = __half22float2(*(const __half2*)&r2.y); acc.z = fmaf(a2, f.x, acc.z); acc.w = fmaf(a2, f.y, acc.w);
            f = __half22float2(*(const __half2*)&r3.x); acc.x = fmaf(a3, f.x, acc.x); acc.y = fmaf(a3, f.y, acc.y);
            f = __half22float2(*(const __half2*)&r3.y); acc.z = fmaf(a3, f.x, acc.z); acc.w = fmaf(a3, f.y, acc.w);
        }
        for (; j < nb; j++) {
            int sj = s_src[warp][j];
            float a = s_alpha[warp][j][myh];
            uint2 r = *(const uint2*)&hh[sj * HD + lane * 4];
            float2 f01 = __half22float2(*(const __half2*)&r.x);
            float2 f23 = __half22float2(*(const __half2*)&r.y);
            acc.x = fmaf(a, f01.x, acc.x);
            acc.y = fmaf(a, f01.y, acc.y);
            acc.z = fmaf(a, f23.x, acc.z);
            acc.w = fmaf(a, f23.y, acc.w);
        }
        __syncwarp();
    }

    // reduce over heads
    acc.x += __shfl_xor_sync(0xffffffffu, acc.x, 8);
    acc.y += __shfl_xor_sync(0xffffffffu, acc.y, 8);
    acc.z += __shfl_xor_sync(0xffffffffu, acc.z, 8);
    acc.w += __shfl_xor_sync(0xffffffffu, acc.w, 8);
    acc.x += __shfl_xor_sync(0xffffffffu, acc.x, 16);
    acc.y += __shfl_xor_sync(0xffffffffu, acc.y, 16);
    acc.z += __shfl_xor_sync(0xffffffffu, acc.z, 16);
    acc.w += __shfl_xor_sync(0xffffffffu, acc.w, 16);

    if (lane < 8) {
        float4 b4 = *(const float4*)&bias[lane * 4];
        float4 o;
        o.x = acc.x * 0.25f + b4.x;
        o.y = acc.y * 0.25f + b4.y;
        o.z = acc.z * 0.25f + b4.z;
        o.w = acc.w * 0.25f + b4.w;
        *(float4*)&out[n * OUT_DIM + lane * 4] = o;
    }
}

// ---------------- launch ----------------
extern "C" void kernel_launch(void* const* d_in, const int* in_sizes, int n_in,
                              void* d_out, int out_size) {
    const float* x    = (const float*)d_in[0];
    const int*   ei   = (const int*)  d_in[1];
    const float* ea   = (const float*)d_in[2];
    const float* Wl   = (const float*)d_in[3];
    const float* as   = (const float*)d_in[4];
    const float* ad   = (const float*)d_in[5];
    const float* bias = (const float*)d_in[6];
    const float* We   = (const float*)d_in[7];
    float* out = (float*)d_out;

    k_zero  <<<(N_NODES + 255) / 256, 256>>>();
    k_transW<<<IN_DIM, HD>>>(Wl);
    k_gemm  <<<(N_NODES + 127) / 128, 256>>>(x, as, ad);
    k_hist  <<<(N_EDGES + 511) / 512, 512>>>(ei);
    k_scan1 <<<SCAN_NB, 256>>>();
    k_scan2 <<<1, 1>>>();
    k_scan3 <<<SCAN_NB, 256>>>();
    k_edge  <<<(N_EDGES + 255) / 256, 256>>>(ei, ea, We);
    k_agg   <<<(N_NODES + 7) / 8, 256>>>(bias, out);
}

// round 5
// speedup vs baseline: 1.0855x; 1.0012x over previous
#include <cuda_runtime.h>
#include <cuda_fp16.h>

#define N_NODES 50000
#define N_EDGES 1600000
#define IN_DIM 128
#define OUT_DIM 32
#define HEADS 4
#define HD 128           // HEADS * OUT_DIM
#define EDGE_DIM 16

#define SCAN_CHUNK 512
#define SCAN_NB 98       // ceil(50000/512)

// ---------------- device scratch (static: no allocation allowed) ----------------
__device__ __half g_hh[N_NODES * HD];         // 12.8 MB  h (fp16)
__device__ float g_WT[IN_DIM * HD];           // 64 KB
__device__ float g_asrc[N_NODES * HEADS];
__device__ float g_adst[N_NODES * HEADS];
__device__ int   g_cnt[N_NODES];
__device__ int   g_off[N_NODES + 1];
__device__ int   g_rank[N_EDGES];             // 6.4 MB rank of edge within its dst segment
__device__ int   g_blocksum[SCAN_NB];
__device__ int   g_csr_src[N_EDGES];          // 6.4 MB
__device__ uint2 g_csr_exp[N_EDGES];          // 12.8 MB: 4 x fp16 exp(logit) per edge

// ---------------- small utility kernels ----------------
__global__ void k_zero() {
    int i = blockIdx.x * blockDim.x + threadIdx.x;
    if (i < N_NODES) g_cnt[i] = 0;
}

__global__ void k_transW(const float* __restrict__ W) {
    int j = blockIdx.x;
    int k = threadIdx.x;
    g_WT[k * HD + j] = W[j * IN_DIM + k];
}

// ---------------- GEMM: 128-node x 128-col tile, 256 thr, 8x8 per thread ----------------
__global__ __launch_bounds__(256) void k_gemm(const float* __restrict__ x,
                                              const float* __restrict__ att_src,
                                              const float* __restrict__ att_dst) {
    __shared__ float ws[32][136];   // W chunk [kk][j], padded
    __shared__ float xs[128][33];   // x chunk [n][kk], padded

    int tid = threadIdx.x;
    int tx = tid & 15;      // cols tx*8 .. tx*8+7
    int ty = tid >> 4;      // nodes ty*8 .. ty*8+7
    int n0 = blockIdx.x * 128;

    float avs[8], avd[8];
    {
        float4 s0 = __ldg((const float4*)&att_src[tx * 8]);
        float4 s1 = __ldg((const float4*)&att_src[tx * 8 + 4]);
        float4 d0 = __ldg((const float4*)&att_dst[tx * 8]);
        float4 d1 = __ldg((const float4*)&att_dst[tx * 8 + 4]);
        avs[0]=s0.x; avs[1]=s0.y; avs[2]=s0.z; avs[3]=s0.w;
        avs[4]=s1.x; avs[5]=s1.y; avs[6]=s1.z; avs[7]=s1.w;
        avd[0]=d0.x; avd[1]=d0.y; avd[2]=d0.z; avd[3]=d0.w;
        avd[4]=d1.x; avd[5]=d1.y; avd[6]=d1.z; avd[7]=d1.w;
    }

    float acc[8][8];
#pragma unroll
    for (int i = 0; i < 8; i++)
#pragma unroll
        for (int j = 0; j < 8; j++) acc[i][j] = 0.f;

    for (int kc = 0; kc < IN_DIM; kc += 32) {
        __syncthreads();
        for (int i = tid; i < 32 * HD; i += 256) {
            int kk = i >> 7, j = i & 127;
            ws[kk][j] = g_WT[(kc + kk) * HD + j];
        }
        for (int i = tid; i < 128 * 32; i += 256) {
            int nn = i >> 5, kk = i & 31;
            int gn = n0 + nn;
            xs[nn][kk] = (gn < N_NODES) ? x[gn * IN_DIM + kc + kk] : 0.f;
        }
        __syncthreads();

#pragma unroll 4
        for (int kk = 0; kk < 32; kk++) {
            float4 w0 = *(const float4*)&ws[kk][tx * 8];
            float4 w1 = *(const float4*)&ws[kk][tx * 8 + 4];
            float wv[8] = {w0.x, w0.y, w0.z, w0.w, w1.x, w1.y, w1.z, w1.w};
            float xv[8];
#pragma unroll
            for (int i = 0; i < 8; i++) xv[i] = xs[ty * 8 + i][kk];
#pragma unroll
            for (int i = 0; i < 8; i++)
#pragma unroll
                for (int j = 0; j < 8; j++)
                    acc[i][j] = fmaf(xv[i], wv[j], acc[i][j]);
        }
    }

    // fused attention terms: shuffle-reduce over the 4 lanes covering one head
    float ps[8], pd[8];
#pragma unroll
    for (int i = 0; i < 8; i++) {
        float s = 0.f, d = 0.f;
#pragma unroll
        for (int j = 0; j < 8; j++) {
            s = fmaf(acc[i][j], avs[j], s);
            d = fmaf(acc[i][j], avd[j], d);
        }
        ps[i] = s; pd[i] = d;
    }
#pragma unroll
    for (int off = 1; off < 4; off <<= 1) {
#pragma unroll
        for (int i = 0; i < 8; i++) {
            ps[i] += __shfl_xor_sync(0xffffffffu, ps[i], off);
            pd[i] += __shfl_xor_sync(0xffffffffu, pd[i], off);
        }
    }
    int head = tx >> 2;
    bool wr_att = ((tx & 3) == 0);

#pragma unroll
    for (int i = 0; i < 8; i++) {
        int gn = n0 + ty * 8 + i;
        if (gn < N_NODES) {
            __half2 h0 = __floats2half2_rn(acc[i][0], acc[i][1]);
            __half2 h1 = __floats2half2_rn(acc[i][2], acc[i][3]);
            __half2 h2 = __floats2half2_rn(acc[i][4], acc[i][5]);
            __half2 h3 = __floats2half2_rn(acc[i][6], acc[i][7]);
            uint4 v;
            v.x = *(const unsigned*)&h0;
            v.y = *(const unsigned*)&h1;
            v.z = *(const unsigned*)&h2;
            v.w = *(const unsigned*)&h3;
            *(uint4*)&g_hh[gn * HD + tx * 8] = v;
            if (wr_att) {
                g_asrc[gn * HEADS + head] = ps[i];
                g_adst[gn * HEADS + head] = pd[i];
            }
        }
    }
}

// ---------------- histogram of dst + rank assignment ----------------
__global__ void k_hist(const int* __restrict__ ei) {
    int e = blockIdx.x * blockDim.x + threadIdx.x;
    if (e < N_EDGES) {
        int d = ei[N_EDGES + e];
        g_rank[e] = atomicAdd(&g_cnt[d], 1);
    }
}

// ---------------- 3-phase exclusive scan of counts ----------------
__global__ void k_scan1() {
    __shared__ int sh[256];
    int b = blockIdx.x, t = threadIdx.x;
    int base = b * SCAN_CHUNK;
    int i0 = base + 2 * t, i1 = i0 + 1;
    int s = 0;
    if (i0 < N_NODES) s += g_cnt[i0];
    if (i1 < N_NODES) s += g_cnt[i1];
    sh[t] = s;
    __syncthreads();
    for (int off = 128; off > 0; off >>= 1) {
        if (t < off) sh[t] += sh[t + off];
        __syncthreads();
    }
    if (t == 0) g_blocksum[b] = sh[0];
}

__global__ void k_scan2() {
    int run = 0;
    for (int b = 0; b < SCAN_NB; b++) {
        int v = g_blocksum[b];
        g_blocksum[b] = run;
        run += v;
    }
}

__global__ void k_scan3() {
    __shared__ int sh[256];
    int b = blockIdx.x, t = threadIdx.x;
    int base = b * SCAN_CHUNK;
    int i0 = base + 2 * t, i1 = i0 + 1;
    int c0 = (i0 < N_NODES) ? g_cnt[i0] : 0;
    int c1 = (i1 < N_NODES) ? g_cnt[i1] : 0;
    int mys = c0 + c1;
    sh[t] = mys;
    __syncthreads();
    for (int off = 1; off < 256; off <<= 1) {
        int v = (t >= off) ? sh[t - off] : 0;
        __syncthreads();
        sh[t] += v;
        __syncthreads();
    }
    int excl = sh[t] - mys + g_blocksum[b];
    if (i0 < N_NODES) g_off[i0] = excl;
    if (i1 < N_NODES) g_off[i1] = excl + c0;
    if (b == 0 && t == 0) g_off[N_NODES] = N_EDGES;
}

// ---------------- edge pass: logits -> exp (fp16) + CSR scatter, no atomics ----------------
__global__ __launch_bounds__(256) void k_edge(const int* __restrict__ ei,
                                              const float* __restrict__ ea,
                                              const float* __restrict__ Wedge) {
    __shared__ float we[HEADS * EDGE_DIM];
    if (threadIdx.x < HEADS * EDGE_DIM) we[threadIdx.x] = Wedge[threadIdx.x];
    __syncthreads();

    int e = blockIdx.x * blockDim.x + threadIdx.x;
    if (e >= N_EDGES) return;

    int src = ei[e];
    int dst = ei[N_EDGES + e];

    const float4* ep = (const float4*)&ea[e * EDGE_DIM];
    float4 e0 = ep[0], e1 = ep[1], e2 = ep[2], e3 = ep[3];
    float ev[16] = {e0.x, e0.y, e0.z, e0.w, e1.x, e1.y, e1.z, e1.w,
                    e2.x, e2.y, e2.z, e2.w, e3.x, e3.y, e3.z, e3.w};

    float lg[4];
#pragma unroll
    for (int h = 0; h < 4; h++) {
        float s = 0.f;
#pragma unroll
        for (int k = 0; k < 16; k++) s = fmaf(ev[k], we[h * 16 + k], s);
        lg[h] = s;
    }

    float4 a4 = *(const float4*)&g_asrc[src * 4];
    float4 b4 = *(const float4*)&g_adst[dst * 4];
    lg[0] += a4.x + b4.x;
    lg[1] += a4.y + b4.y;
    lg[2] += a4.z + b4.z;
    lg[3] += a4.w + b4.w;
#pragma unroll
    for (int h = 0; h < 4; h++) {
        float v = (lg[h] > 0.f) ? lg[h] : 0.2f * lg[h];
        lg[h] = __expf(v);
    }

    int pos = g_off[dst] + g_rank[e];
    g_csr_src[pos] = src;
    __half2 x01 = __floats2half2_rn(lg[0], lg[1]);
    __half2 x23 = __floats2half2_rn(lg[2], lg[3]);
    uint2 pk;
    pk.x = *(const unsigned*)&x01;
    pk.y = *(const unsigned*)&x23;
    g_csr_exp[pos] = pk;
}

// ---------------- aggregation: warp per node, MLP-unrolled fp16 gather ----------------
__global__ __launch_bounds__(256) void k_agg(const float* __restrict__ bias,
                                             float* __restrict__ out) {
    __shared__ float s_alpha[8][32][4];
    __shared__ int   s_src[8][32];

    int warp = threadIdx.x >> 5;
    int lane = threadIdx.x & 31;
    int n = blockIdx.x * 8 + warp;
    if (n >= N_NODES) return;

    int beg = g_off[n];
    int end = g_off[n + 1];
    int myh = lane >> 3;

    // pass 1: denom per head (exp already computed, fp16)
    float d0 = 0.f, d1 = 0.f, d2 = 0.f, d3 = 0.f;
    for (int i = beg + lane; i < end; i += 32) {
        uint2 r = g_csr_exp[i];
        float2 f01 = __half22float2(*(const __half2*)&r.x);
        float2 f23 = __half22float2(*(const __half2*)&r.y);
        d0 += f01.x; d1 += f01.y; d2 += f23.x; d3 += f23.y;
    }
#pragma unroll
    for (int off = 16; off > 0; off >>= 1) {
        d0 += __shfl_xor_sync(0xffffffffu, d0, off);
        d1 += __shfl_xor_sync(0xffffffffu, d1, off);
        d2 += __shfl_xor_sync(0xffffffffu, d2, off);
        d3 += __shfl_xor_sync(0xffffffffu, d3, off);
    }
    float i0 = 1.f / (d0 + 1e-16f);
    float i1 = 1.f / (d1 + 1e-16f);
    float i2 = 1.f / (d2 + 1e-16f);
    float i3 = 1.f / (d3 + 1e-16f);

    // pass 2: alpha-weighted gather of h[src], 4 loads in flight
    float4 acc = {0.f, 0.f, 0.f, 0.f};
    const __half* hh = g_hh;
    for (int c = beg; c < end; c += 32) {
        int i = c + lane;
        int nb = min(32, end - c);
        if (lane < nb) {
            uint2 r = g_csr_exp[i];
            float2 f01 = __half22float2(*(const __half2*)&r.x);
            float2 f23 = __half22float2(*(const __half2*)&r.y);
            s_src[warp][lane] = g_csr_src[i];
            s_alpha[warp][lane][0] = f01.x * i0;
            s_alpha[warp][lane][1] = f01.y * i1;
            s_alpha[warp][lane][2] = f23.x * i2;
            s_alpha[warp][lane][3] = f23.y * i3;
        }
        __syncwarp();
        int j = 0;
        for (; j + 4 <= nb; j += 4) {
            int sj0 = s_src[warp][j + 0];
            int sj1 = s_src[warp][j + 1];
            int sj2 = s_src[warp][j + 2];
            int sj3 = s_src[warp][j + 3];
            uint2 r0 = *(const uint2*)&hh[sj0 * HD + lane * 4];
            uint2 r1 = *(const uint2*)&hh[sj1 * HD + lane * 4];
            uint2 r2 = *(const uint2*)&hh[sj2 * HD + lane * 4];
            uint2 r3 = *(const uint2*)&hh[sj3 * HD + lane * 4];
            float a0 = s_alpha[warp][j + 0][myh];
            float a1 = s_alpha[warp][j + 1][myh];
            float a2 = s_alpha[warp][j + 2][myh];
            float a3 = s_alpha[warp][j + 3][myh];
            float2 f;
            f = __half22float2(*(const __half2*)&r0.x); acc.x = fmaf(a0, f.x, acc.x); acc.y = fmaf(a0, f.y, acc.y);
            f = __half22float2(*(const __half2*)&r0.y); acc.z = fmaf(a0, f.x, acc.z); acc.w = fmaf(a0, f.y, acc.w);
            f = __half22float2(*(const __half2*)&r1.x); acc.x = fmaf(a1, f.x, acc.x); acc.y = fmaf(a1, f.y, acc.y);
            f = __half22float2(*(const __half2*)&r1.y); acc.z = fmaf(a1, f.x, acc.z); acc.w = fmaf(a1, f.y, acc.w);
            f = __half22float2(*(const __half2*)&r2.x); acc.x = fmaf(a2, f.x, acc.x); acc.y = fmaf(a2, f.y, acc.y);
            f = __half22float2(*(const __half2*)&r2.y); acc.z = fmaf(a2, f.x, acc.z); acc.w = fmaf(a2, f.y, acc.w);
            f = __half22float2(*(const __half2*)&r3.x); acc.x = fmaf(a3, f.x, acc.x); acc.y = fmaf(a3, f.y, acc.y);
            f = __half22float2(*(const __half2*)&r3.y); acc.z = fmaf(a3, f.x, acc.z); acc.w = fmaf(a3, f.y, acc.w);
        }
        for (; j < nb; j++) {
            int sj = s_src[warp][j];
            float a = s_alpha[warp][j][myh];
            uint2 r = *(const uint2*)&hh[sj * HD + lane * 4];
            float2 f01 = __half22float2(*(const __half2*)&r.x);
            float2 f23 = __half22float2(*(const __half2*)&r.y);
            acc.x = fmaf(a, f01.x, acc.x);
            acc.y = fmaf(a, f01.y, acc.y);
            acc.z = fmaf(a, f23.x, acc.z);
            acc.w = fmaf(a, f23.y, acc.w);
        }
        __syncwarp();
    }

    // reduce over heads
    acc.x += __shfl_xor_sync(0xffffffffu, acc.x, 8);
    acc.y += __shfl_xor_sync(0xffffffffu, acc.y, 8);
    acc.z += __shfl_xor_sync(0xffffffffu, acc.z, 8);
    acc.w += __shfl_xor_sync(0xffffffffu, acc.w, 8);
    acc.x += __shfl_xor_sync(0xffffffffu, acc.x, 16);
    acc.y += __shfl_xor_sync(0xffffffffu, acc.y, 16);
    acc.z += __shfl_xor_sync(0xffffffffu, acc.z, 16);
    acc.w += __shfl_xor_sync(0xffffffffu, acc.w, 16);

    if (lane < 8) {
        float4 b4 = *(const float4*)&bias[lane * 4];
        float4 o;
        o.x = acc.x * 0.25f + b4.x;
        o.y = acc.y * 0.25f + b4.y;
        o.z = acc.z * 0.25f + b4.z;
        o.w = acc.w * 0.25f + b4.w;
        *(float4*)&out[n * OUT_DIM + lane * 4] = o;
    }
}

// ---------------- launch ----------------
extern "C" void kernel_launch(void* const* d_in, const int* in_sizes, int n_in,
                              void* d_out, int out_size) {
    const float* x    = (const float*)d_in[0];
    const int*   ei   = (const int*)  d_in[1];
    const float* ea   = (const float*)d_in[2];
    const float* Wl   = (const float*)d_in[3];
    const float* as   = (const float*)d_in[4];
    const float* ad   = (const float*)d_in[5];
    const float* bias = (const float*)d_in[6];
    const float* We   = (const float*)d_in[7];
    float* out = (float*)d_out;

    k_zero  <<<(N_NODES + 255) / 256, 256>>>();
    k_transW<<<IN_DIM, HD>>>(Wl);
    k_gemm  <<<(N_NODES + 127) / 128, 256>>>(x, as, ad);
    k_hist  <<<(N_EDGES + 511) / 512, 512>>>(ei);
    k_scan1 <<<SCAN_NB, 256>>>();
    k_scan2 <<<1, 1>>>();
    k_scan3 <<<SCAN_NB, 256>>>();
    k_edge  <<<(N_EDGES + 255) / 256, 256>>>(ei, ea, We);
    k_agg   <<<(N_NODES + 7) / 8, 256>>>(bias, out);
}